// round 9
// baseline (speedup 1.0000x reference)
#include <cuda_runtime.h>
#include <cstdint>

#define MAXN 50000
#define MAXE 600000

// ---------------- scratch ----------------
__device__ __align__(16) float g_deg[MAXN];        // dinv = rsqrt(1 + indeg)
__device__ int   g_cnt[MAXN];
__device__ int   g_off[MAXN + 1];
__device__ int   g_pos[MAXN];
__device__ int   g_csr[MAXE];
__device__ int   g_bsum[256];
__device__ __align__(16) float g_agg[MAXN * 128];
__device__ __align__(16) float g_t  [MAXN * 128];
__device__ __align__(16) float g_t3 [MAXN * 2];
__device__ int g_is32 = 0;   // probe only ever sets 1 (idempotent across graph replays)

// ---------------- graph prep ----------------
__global__ void k_init(const unsigned* __restrict__ w, int n) {
    int i = blockIdx.x * blockDim.x + threadIdx.x;
    if (i < n) g_cnt[i] = 0;
    if (i < 2048 && w[2 * i + 1] != 0u) g_is32 = 1;
}

__device__ __forceinline__ void decode_edge(const void* ei, int e, int E, int N, int& s, int& d) {
    if (g_is32) {
        const int* p = (const int*)ei;
        s = p[e]; d = p[E + e];
    } else {
        const long long* p = (const long long*)ei;
        s = (int)p[e]; d = (int)p[E + e];
    }
    s = min(max(s, 0), N - 1);
    d = min(max(d, 0), N - 1);
}

__global__ void k_count(const void* __restrict__ ei, int E, int N) {
    int e = blockIdx.x * blockDim.x + threadIdx.x;
    if (e >= E) return;
    int s, d;
    decode_edge(ei, e, E, N, s, d);
    atomicAdd(&g_cnt[d], 1);
}

__global__ __launch_bounds__(256) void k_scan1(int N) {
    __shared__ int sh[256];
    int i = blockIdx.x * 256 + threadIdx.x;
    int t = threadIdx.x;
    int v = (i < N) ? g_cnt[i] : 0;
    sh[t] = v;
    __syncthreads();
#pragma unroll
    for (int off = 1; off < 256; off <<= 1) {
        int u = (t >= off) ? sh[t - off] : 0;
        __syncthreads();
        sh[t] += u;
        __syncthreads();
    }
    if (i < N) g_off[i] = sh[t] - v;
    if (t == 255) g_bsum[blockIdx.x] = sh[255];
}

__global__ __launch_bounds__(256) void k_scan23(int nBlocks, int N) {
    __shared__ int sh[256];
    int t = threadIdx.x;
    int v = (t < nBlocks) ? g_bsum[t] : 0;
    sh[t] = v;
    __syncthreads();
#pragma unroll
    for (int off = 1; off < 256; off <<= 1) {
        int u = (t >= off) ? sh[t - off] : 0;
        __syncthreads();
        sh[t] += u;
        __syncthreads();
    }
    int pre = (blockIdx.x > 0) ? sh[blockIdx.x - 1] : 0;
    int i = blockIdx.x * 256 + t;
    if (i < N) {
        int o = g_off[i] + pre;
        g_off[i] = o;
        g_pos[i] = o;
        g_deg[i] = rsqrtf((float)(1 + g_cnt[i]));
    }
    if (blockIdx.x == 0 && t == 0) g_off[N] = sh[nBlocks - 1];
}

__global__ void k_fill(const void* __restrict__ ei, int E, int N) {
    int e = blockIdx.x * blockDim.x + threadIdx.x;
    if (e >= E) return;
    int s, d;
    decode_edge(ei, e, E, N, s, d);
    int p = atomicAdd(&g_pos[d], 1);
    g_csr[p] = s;
}

// ---------------- pull aggregation (C = 128) ----------------
__global__ __launch_bounds__(256) void k_pull128(const float* __restrict__ h,
                                                 float* __restrict__ out, int N) {
    int d = blockIdx.x * (blockDim.x >> 5) + (threadIdx.x >> 5);
    if (d >= N) return;
    int lane = threadIdx.x & 31;
    float dd = g_deg[d];
    float4 acc = ((const float4*)(h + (size_t)d * 128))[lane];
    float nms = dd * dd;
    acc.x *= nms; acc.y *= nms; acc.z *= nms; acc.w *= nms;
    const int beg = g_off[d], end = g_off[d + 1];
    for (int base = beg; base < end; base += 32) {
        int cnt = min(end - base, 32);
        int e = base + lane;
        int sE = (lane < cnt) ? g_csr[e] : 0;
        float nmE = (lane < cnt) ? g_deg[sE] * dd : 0.f;
        int j = 0;
        for (; j + 2 <= cnt; j += 2) {
            int   s0 = __shfl_sync(0xffffffffu, sE,  j);
            int   s1 = __shfl_sync(0xffffffffu, sE,  j + 1);
            float n0 = __shfl_sync(0xffffffffu, nmE, j);
            float n1 = __shfl_sync(0xffffffffu, nmE, j + 1);
            float4 v0 = ((const float4*)(h + (size_t)s0 * 128))[lane];
            float4 v1 = ((const float4*)(h + (size_t)s1 * 128))[lane];
            acc.x += n0 * v0.x + n1 * v1.x;
            acc.y += n0 * v0.y + n1 * v1.y;
            acc.z += n0 * v0.z + n1 * v1.z;
            acc.w += n0 * v0.w + n1 * v1.w;
        }
        if (j < cnt) {
            int   s0 = __shfl_sync(0xffffffffu, sE,  j);
            float n0 = __shfl_sync(0xffffffffu, nmE, j);
            float4 v0 = ((const float4*)(h + (size_t)s0 * 128))[lane];
            acc.x += n0 * v0.x; acc.y += n0 * v0.y;
            acc.z += n0 * v0.z; acc.w += n0 * v0.w;
        }
    }
    ((float4*)(out + (size_t)d * 128))[lane] = acc;
}

// ---------------- fused layer1+layer2 GEMM ----------------
// Per 128-row tile: h1 = relu(agg @ W1 + b1) kept in smem; t = h1 @ W2 -> gmem.
#define H1S_STRIDE 260            // 256 + 4 pad (floats); 16B-aligned rows
#define SM_GEMM_BYTES ((128 * H1S_STRIDE + 2 * 8 * 128) * 4)

__global__ __launch_bounds__(256) void k_gemm12(
    int M,
    const float* __restrict__ A,   // agg [M,128]
    const float* __restrict__ W1,  // [128,256]
    const float* __restrict__ b1,  // [256]
    const float* __restrict__ W2,  // [256,128]
    float* __restrict__ T)         // t [M,128]
{
    extern __shared__ float sm[];
    float* h1s = sm;                          // [128][H1S_STRIDE]
    float* Asf = sm + 128 * H1S_STRIDE;       // [8][128]
    float* Bsf = Asf + 8 * 128;               // [8][128]

    const int tid = threadIdx.x;
    const int mtile = blockIdx.x;
    const int rowA = tid >> 1;            // 0..127
    const int colA = (tid & 1) << 2;      // 0 or 4
    const int rowB = tid >> 5;            // 0..7
    const int colB = (tid & 31) << 2;     // 0..124
    const int tr = (tid >> 4) << 3;
    const int tc = (tid & 15) << 3;

    const int aRow = mtile * 128 + rowA;
    const bool aValid = aRow < M;
    const float* Ag = A + (size_t)aRow * 128 + colA;

    // ================= phase 1: GEMM1, two 128-col tiles of W1 =================
    for (int ct = 0; ct < 2; ct++) {
        const float* Bg = W1 + (size_t)rowB * 256 + ct * 128 + colB;

        unsigned long long acc[8][4];
#pragma unroll
        for (int i = 0; i < 8; i++)
#pragma unroll
            for (int j = 0; j < 4; j++) acc[i][j] = 0ull;

        float4 av = aValid ? *(const float4*)(Ag) : make_float4(0.f, 0.f, 0.f, 0.f);
        float4 bv = *(const float4*)(Bg);
        __syncthreads();                    // smem buffers free (prev ct / prev phase)
        Asf[(colA + 0) * 128 + rowA] = av.x;
        Asf[(colA + 1) * 128 + rowA] = av.y;
        Asf[(colA + 2) * 128 + rowA] = av.z;
        Asf[(colA + 3) * 128 + rowA] = av.w;
        *(float4*)&Bsf[rowB * 128 + colB] = bv;
        __syncthreads();

        for (int k0 = 0; k0 < 128; k0 += 8) {
            const bool more = (k0 + 8) < 128;
            if (more) {
                av = aValid ? *(const float4*)(Ag + k0 + 8) : make_float4(0.f, 0.f, 0.f, 0.f);
                bv = *(const float4*)(Bg + (size_t)(k0 + 8) * 256);
            }
#pragma unroll
            for (int k = 0; k < 8; ++k) {
                float4 ra0 = *(const float4*)&Asf[k * 128 + tr];
                float4 ra1 = *(const float4*)&Asf[k * 128 + tr + 4];
                unsigned long long b2[4];
#pragma unroll
                for (int j = 0; j < 4; j++)
                    b2[j] = *(const unsigned long long*)&Bsf[k * 128 + tc + j * 2];
                float ras[8] = {ra0.x, ra0.y, ra0.z, ra0.w, ra1.x, ra1.y, ra1.z, ra1.w};
#pragma unroll
                for (int i = 0; i < 8; i++) {
                    unsigned long long a2;
                    asm("mov.b64 %0, {%1, %1};" : "=l"(a2) : "f"(ras[i]));
#pragma unroll
                    for (int j = 0; j < 4; j++)
                        asm("fma.rn.f32x2 %0, %1, %2, %3;"
                            : "=l"(acc[i][j]) : "l"(a2), "l"(b2[j]), "l"(acc[i][j]));
                }
            }
            __syncthreads();
            if (more) {
                Asf[(colA + 0) * 128 + rowA] = av.x;
                Asf[(colA + 1) * 128 + rowA] = av.y;
                Asf[(colA + 2) * 128 + rowA] = av.z;
                Asf[(colA + 3) * 128 + rowA] = av.w;
                *(float4*)&Bsf[rowB * 128 + colB] = bv;
                __syncthreads();
            }
        }

        // epilogue: bias + relu -> h1s (row-major)
#pragma unroll
        for (int i = 0; i < 8; i++) {
#pragma unroll
            for (int jj = 0; jj < 2; jj++) {
                int c = ct * 128 + tc + jj * 4;
                float4 v;
                asm("mov.b64 {%0, %1}, %2;" : "=f"(v.x), "=f"(v.y) : "l"(acc[i][jj * 2 + 0]));
                asm("mov.b64 {%0, %1}, %2;" : "=f"(v.z), "=f"(v.w) : "l"(acc[i][jj * 2 + 1]));
                const float4 bb = *(const float4*)(b1 + c);
                v.x = fmaxf(v.x + bb.x, 0.f);
                v.y = fmaxf(v.y + bb.y, 0.f);
                v.z = fmaxf(v.z + bb.z, 0.f);
                v.w = fmaxf(v.w + bb.w, 0.f);
                *(float4*)&h1s[(tr + i) * H1S_STRIDE + c] = v;
            }
        }
    }
    __syncthreads();

    // ================= phase 2: GEMM2, t = h1s @ W2 (K=256, N=128) =================
    {
        const float* Bg = W2 + (size_t)rowB * 128 + colB;

        unsigned long long acc[8][4];
#pragma unroll
        for (int i = 0; i < 8; i++)
#pragma unroll
            for (int j = 0; j < 4; j++) acc[i][j] = 0ull;

        float4 bv = *(const float4*)(Bg);
        *(float4*)&Bsf[rowB * 128 + colB] = bv;
        __syncthreads();

        for (int k0 = 0; k0 < 256; k0 += 8) {
            const bool more = (k0 + 8) < 256;
            if (more) bv = *(const float4*)(Bg + (size_t)(k0 + 8) * 128);
#pragma unroll
            for (int k4 = 0; k4 < 2; k4++) {
                // A: 8 rows x 4 consecutive k from smem h1 tile
                float4 a4[8];
#pragma unroll
                for (int i = 0; i < 8; i++)
                    a4[i] = *(const float4*)&h1s[(tr + i) * H1S_STRIDE + k0 + k4 * 4];
#pragma unroll
                for (int kk = 0; kk < 4; kk++) {
                    int k = k4 * 4 + kk;
                    unsigned long long b2[4];
#pragma unroll
                    for (int j = 0; j < 4; j++)
                        b2[j] = *(const unsigned long long*)&Bsf[k * 128 + tc + j * 2];
#pragma unroll
                    for (int i = 0; i < 8; i++) {
                        float ra = (kk == 0) ? a4[i].x : (kk == 1) ? a4[i].y : (kk == 2) ? a4[i].z : a4[i].w;
                        unsigned long long a2;
                        asm("mov.b64 %0, {%1, %1};" : "=l"(a2) : "f"(ra));
#pragma unroll
                        for (int j = 0; j < 4; j++)
                            asm("fma.rn.f32x2 %0, %1, %2, %3;"
                                : "=l"(acc[i][j]) : "l"(a2), "l"(b2[j]), "l"(acc[i][j]));
                    }
                }
            }
            __syncthreads();
            if (more) {
                *(float4*)&Bsf[rowB * 128 + colB] = bv;
                __syncthreads();
            }
        }

#pragma unroll
        for (int i = 0; i < 8; i++) {
            int r = mtile * 128 + tr + i;
            if (r >= M) break;
#pragma unroll
            for (int jj = 0; jj < 2; jj++) {
                int c = tc + jj * 4;
                float4 v;
                asm("mov.b64 {%0, %1}, %2;" : "=f"(v.x), "=f"(v.y) : "l"(acc[i][jj * 2 + 0]));
                asm("mov.b64 {%0, %1}, %2;" : "=f"(v.z), "=f"(v.w) : "l"(acc[i][jj * 2 + 1]));
                *(float4*)&T[(size_t)r * 128 + c] = v;
            }
        }
    }
}

// ---------------- layer-3: fused bias2+relu, 128 -> 2 ----------------
__global__ void k_gemm3(const float* __restrict__ agg, const float* __restrict__ b2,
                        const float* __restrict__ W3, int M) {
    int node = blockIdx.x * (blockDim.x >> 5) + (threadIdx.x >> 5);
    if (node >= M) return;
    int lane = threadIdx.x & 31;
    float4 v  = ((const float4*)(agg + (size_t)node * 128))[lane];
    float4 bb = ((const float4*)b2)[lane];
    v.x = fmaxf(v.x + bb.x, 0.f);
    v.y = fmaxf(v.y + bb.y, 0.f);
    v.z = fmaxf(v.z + bb.z, 0.f);
    v.w = fmaxf(v.w + bb.w, 0.f);
    int k = lane * 4;
    float a0 = v.x * W3[2 * k + 0] + v.y * W3[2 * k + 2] + v.z * W3[2 * k + 4] + v.w * W3[2 * k + 6];
    float a1 = v.x * W3[2 * k + 1] + v.y * W3[2 * k + 3] + v.z * W3[2 * k + 5] + v.w * W3[2 * k + 7];
#pragma unroll
    for (int o = 16; o; o >>= 1) {
        a0 += __shfl_xor_sync(0xffffffffu, a0, o);
        a1 += __shfl_xor_sync(0xffffffffu, a1, o);
    }
    if (lane == 0) {
        g_t3[node * 2 + 0] = a0;
        g_t3[node * 2 + 1] = a1;
    }
}

// ---------------- layer-3 pull + log_softmax fused ----------------
__global__ void k_pull2_lsm(const float* __restrict__ b3, float* __restrict__ out, int N) {
    int d = blockIdx.x * blockDim.x + threadIdx.x;
    if (d >= N) return;
    float dd = g_deg[d];
    float a0 = dd * dd * g_t3[2 * d + 0];
    float a1 = dd * dd * g_t3[2 * d + 1];
    int beg = g_off[d], end = g_off[d + 1];
    for (int i = beg; i < end; i++) {
        int s = g_csr[i];
        float nm = g_deg[s] * dd;
        a0 += nm * g_t3[2 * s + 0];
        a1 += nm * g_t3[2 * s + 1];
    }
    a0 += b3[0];
    a1 += b3[1];
    float m = fmaxf(a0, a1);
    float l = m + logf(expf(a0 - m) + expf(a1 - m));
    out[2 * d + 0] = a0 - l;
    out[2 * d + 1] = a1 - l;
}

// ---------------- orchestration ----------------
extern "C" void kernel_launch(void* const* d_in, const int* in_sizes, int n_in,
                              void* d_out, int out_size)
{
    const float* x  = (const float*)d_in[0];
    const float* W1 = (const float*)d_in[1];
    const float* b1 = (const float*)d_in[2];
    const float* W2 = (const float*)d_in[3];
    const float* b2 = (const float*)d_in[4];
    const float* W3 = (const float*)d_in[5];
    const float* b3 = (const float*)d_in[6];
    const void*  ei = (const void*)d_in[7];
    float* out = (float*)d_out;

    const int IN = 128;
    const int N  = in_sizes[0] / IN;       // 50000
    const int E  = in_sizes[7] / 2;        // 600000
    (void)n_in; (void)out_size;

    float *p_agg, *p_t;
    cudaGetSymbolAddress((void**)&p_agg, g_agg);
    cudaGetSymbolAddress((void**)&p_t,   g_t);

    cudaFuncSetAttribute(k_gemm12, cudaFuncAttributeMaxDynamicSharedMemorySize, SM_GEMM_BYTES);

    const int T = 256;
    const int nodeBlocks  = (N + T - 1) / T;     // 196
    const int edgeBlocks  = (E + T - 1) / T;
    const int warpBlocksN = (N + 7) / 8;
    const int mTiles      = (N + 127) / 128;     // 391

    // graph prep
    k_init<<<nodeBlocks, T>>>((const unsigned*)ei, N);
    k_count<<<edgeBlocks, T>>>(ei, E, N);
    k_scan1<<<nodeBlocks, T>>>(N);
    k_scan23<<<nodeBlocks, T>>>(nodeBlocks, N);
    k_fill<<<edgeBlocks, T>>>(ei, E, N);

    // ---- layer 1+2 fused:  agg = A x ;  t = relu((agg)W1 + b1) W2 ----
    k_pull128<<<warpBlocksN, T>>>(x, p_agg, N);
    k_gemm12<<<mTiles, 256, SM_GEMM_BYTES>>>(N, p_agg, W1, b1, W2, p_t);
    k_pull128<<<warpBlocksN, T>>>(p_t, p_agg, N);

    // ---- layer 3: h2 = relu(agg+b2) fused; t3 = h2 W3 ; out = lsm(A t3 + b3) ----
    k_gemm3<<<warpBlocksN, T>>>(p_agg, b2, W3, N);
    k_pull2_lsm<<<nodeBlocks, T>>>(b3, out, N);
}